// round 17
// baseline (speedup 1.0000x reference)
#include <cuda_runtime.h>
#include <cuda_bf16.h>
#include <cuda_fp16.h>
#include <cstdint>

#define BATCH 16
#define SEQ   2048
#define DIM   128
#define TILE  128
#define NT    (SEQ/TILE)
#define SCALE 0.088388347648318447f
#define LDE   136                 // 16-bit elements per padded smem row
#define NELEM (BATCH*SEQ*DIM)

#define T_ELEMS (TILE*LDE)
#define OFF_K   0
#define OFF_Q   (1*T_ELEMS)      /* reused as P(fp16) staging after MMA1 */
#define OFF_V   (2*T_ELEMS)
#define OFF_SL  (3*T_ELEMS)      // 256 floats: per-half row sums
#define SMEM_BYTES (3*T_ELEMS*2 + 256*4)

// pre-converted fp16 inputs
static __device__ __half g_q16[NELEM];
static __device__ __half g_k16[NELEM];
static __device__ __half g_v16[NELEM];

__device__ __forceinline__ uint32_t smem_u32(const void* p) {
    uint32_t a;
    asm("{ .reg .u64 t; cvta.to.shared.u64 t, %1; cvt.u32.u64 %0, t; }" : "=r"(a) : "l"(p));
    return a;
}
__device__ __forceinline__ void cpa16(uint32_t dst, const void* src) {
    asm volatile("cp.async.cg.shared.global [%0], [%1], 16;" :: "r"(dst), "l"(src));
}
__device__ __forceinline__ void cpa_commit() {
    asm volatile("cp.async.commit_group;" ::: "memory");
}
__device__ __forceinline__ void cpa_wait_all() {
    asm volatile("cp.async.wait_group 0;" ::: "memory");
}
__device__ __forceinline__ void ldsm4(uint32_t* r, uint32_t addr) {
    asm volatile("ldmatrix.sync.aligned.m8n8.x4.shared.b16 {%0,%1,%2,%3}, [%4];"
                 : "=r"(r[0]), "=r"(r[1]), "=r"(r[2]), "=r"(r[3]) : "r"(addr));
}
__device__ __forceinline__ void ldsm4t(uint32_t* r, uint32_t addr) {
    asm volatile("ldmatrix.sync.aligned.m8n8.x4.trans.shared.b16 {%0,%1,%2,%3}, [%4];"
                 : "=r"(r[0]), "=r"(r[1]), "=r"(r[2]), "=r"(r[3]) : "r"(addr));
}
__device__ __forceinline__ void mma_f16(float* d, const uint32_t* a, const uint32_t* b) {
    asm volatile("mma.sync.aligned.m16n8k16.row.col.f32.f16.f16.f32 "
                 "{%0,%1,%2,%3}, {%4,%5,%6,%7}, {%8,%9}, {%0,%1,%2,%3};"
                 : "+f"(d[0]), "+f"(d[1]), "+f"(d[2]), "+f"(d[3])
                 : "r"(a[0]), "r"(a[1]), "r"(a[2]), "r"(a[3]), "r"(b[0]), "r"(b[1]));
}
__device__ __forceinline__ uint32_t pack_h2(float a, float b) {
    __half2 t = __floats2half2_rn(a, b);
    return *(uint32_t*)&t;
}

// ---------------- pre-pass: Q/K/V -> fp16 ----------------
__global__ __launch_bounds__(256)
void conv_pre_kernel(const float* __restrict__ Q, const float* __restrict__ K,
                     const float* __restrict__ V) {
    const int t = blockIdx.y;
    const float* X = (t == 0) ? Q : ((t == 1) ? K : V);
    __half* D = (t == 0) ? g_q16 : ((t == 1) ? g_k16 : g_v16);
    const size_t i4 = (size_t)blockIdx.x * blockDim.x + threadIdx.x;
    const float4 v = ((const float4*)X)[i4];
    __half2 a = __floats2half2_rn(v.x, v.y);
    __half2 b = __floats2half2_rn(v.z, v.w);
    uint2 o; o.x = *(uint32_t*)&a; o.y = *(uint32_t*)&b;
    ((uint2*)D)[i4] = o;
}

// ---------------- main kernel: 2 CTAs/SM co-residency ----------------
__global__ __launch_bounds__(512, 2)
void attn_mma_kernel(float* __restrict__ outp, float* __restrict__ wts) {
    extern __shared__ __align__(16) char smem_raw[];
    __half* sb = (__half*)smem_raw;
    float* sL = (float*)(sb + OFF_SL);      // [2][128]
    const uint32_t su = smem_u32(smem_raw);

    const int tid = threadIdx.x;
    const int wid = tid >> 5;               // 0..15
    const int l   = tid & 31;
    const int m   = wid & 7;
    const int h   = wid >> 3;
    const int m0  = m * 16;
    const int b   = blockIdx.y;

    // cost-permuted i-tile map: co-resident bids (Δ=148 -> Δit=4 mod 16) get
    // near-constant combined work
    const int ITMAP[16] = {0,8,1,9,15,7,14,6,4,12,5,13,11,3,10,2};
    const int it = ITMAP[blockIdx.x];

    const int g   = l >> 3, r = l & 7;
    const int gb0 = g & 1, gb1 = g >> 1;
    const int ar  = l >> 2, ac = l & 3;

    const int offA = (m0 + gb0 * 8 + r) * LDE + gb1 * 8;
    const int offB = (gb1 * 8 + r) * LDE + gb0 * 8;
    const int offV = (gb0 * 8 + r) * LDE + gb1 * 8;

    const int crow0 = tid >> 4;             // 0..31
    const int ccol0 = (tid & 15) * 8;

    const int i0 = it * TILE;
    const int gi0 = i0 + m0 + ar;

    // ---- K tile via cp.async ----
    {
        const size_t base = (size_t)(b * SEQ + i0) * DIM;
        #pragma unroll
        for (int i = 0; i < 4; i++) {
            const int row = crow0 + i * 32;
            const uint32_t ds = su + (uint32_t)((row * LDE + ccol0) << 1);
            cpa16(ds + (OFF_K << 1), g_k16 + base + (size_t)row * DIM + ccol0);
        }
        cpa_commit();
    }

    // ---- zero-fill lower-triangle cols [0, i0) ----
    {
        const int W0 = i0 / 4;
        const float4 z4 = make_float4(0.0f, 0.0f, 0.0f, 0.0f);
        for (int row = wid; row < TILE; row += 16) {
            float4* wr = (float4*)(wts + ((size_t)(b * SEQ + i0 + row)) * SEQ);
            for (int q = l; q < W0; q += 32) wr[q] = z4;
        }
    }

    float Oa[8][4];
    #pragma unroll
    for (int nb = 0; nb < 8; nb++)
        #pragma unroll
        for (int e = 0; e < 4; e++) Oa[nb][e] = 0.0f;
    float ls0 = 0.0f, ls1 = 0.0f;

    #pragma unroll 1
    for (int jt = it; jt < NT; jt++) {
        const int j0 = jt * TILE;
        __syncthreads();

        // ---- Q + V (fp16) via cp.async ----
        {
            const size_t base = (size_t)(b * SEQ + j0) * DIM;
            #pragma unroll
            for (int i = 0; i < 4; i++) {
                const int row = crow0 + i * 32;
                const uint32_t ds = su + (uint32_t)((row * LDE + ccol0) << 1);
                const size_t gofs = base + (size_t)row * DIM + ccol0;
                cpa16(ds + (OFF_Q << 1), g_q16 + gofs);
                cpa16(ds + (OFF_V << 1), g_v16 + gofs);
            }
            cpa_commit();
            cpa_wait_all();
        }
        __syncthreads();

        // ---- MMA1 (fp16): S = K . Q^T ----
        float S[8][4];
        #pragma unroll
        for (int nb = 0; nb < 8; nb++)
            #pragma unroll
            for (int e = 0; e < 4; e++) S[nb][e] = 0.0f;

        #pragma unroll
        for (int ks = 0; ks < 8; ks++) {
            uint32_t ak[4];
            ldsm4(ak, su + (uint32_t)((OFF_K + offA + ks * 16) << 1));
            #pragma unroll
            for (int nbp = 0; nbp < 4; nbp++) {
                const int nbg = h * 4 + nbp;
                uint32_t bq[4];
                ldsm4(bq, su + (uint32_t)((OFF_Q + offB + nbg * 16 * LDE + ks * 16) << 1));
                mma_f16(S[2 * nbp],     ak, bq);
                mma_f16(S[2 * nbp + 1], ak, bq + 2);
            }
        }
        __syncthreads();   // Q reads done before P staging overwrites

        // ---- epilogue: exp, mask, STG weights, stage P (fp16) ----
        const bool diag = (jt == it);
        const int cb = h * 64 + 2 * ac;
        float* wr0 = wts + ((size_t)(b * SEQ + gi0)) * SEQ + j0 + cb;
        float* wr1 = wr0 + (size_t)8 * SEQ;
        #pragma unroll
        for (int nb = 0; nb < 8; nb++) {
            float p0 = __expf(S[nb][0] * SCALE);
            float p1 = __expf(S[nb][1] * SCALE);
            float p2 = __expf(S[nb][2] * SCALE);
            float p3 = __expf(S[nb][3] * SCALE);
            const int j = j0 + cb + nb * 8;
            if (diag) {
                if (j     < gi0)     p0 = 0.0f;
                if (j + 1 < gi0)     p1 = 0.0f;
                if (j     < gi0 + 8) p2 = 0.0f;
                if (j + 1 < gi0 + 8) p3 = 0.0f;
            }
            ls0 += p0 + p1;
            ls1 += p2 + p3;
            *(float2*)(wr0 + nb * 8) = make_float2(p0, p1);
            *(float2*)(wr1 + nb * 8) = make_float2(p2, p3);
            const int e0 = (m0 + ar) * LDE + cb + nb * 8;
            const int e1 = e0 + 8 * LDE;
            *(uint32_t*)(sb + OFF_Q + e0) = pack_h2(p0, p1);
            *(uint32_t*)(sb + OFF_Q + e1) = pack_h2(p2, p3);
        }
        __syncthreads();   // P staged; both halves visible

        // ---- MMA2 (fp16): O += P . V ----
        #pragma unroll
        for (int kb = 0; kb < 8; kb++) {
            uint32_t aP[4];
            ldsm4(aP, su + (uint32_t)((OFF_Q + offA + kb * 16) << 1));
            #pragma unroll
            for (int dbp = 0; dbp < 4; dbp++) {
                const int dbg = h * 4 + dbp;
                uint32_t bv[4];
                ldsm4t(bv, su + (uint32_t)((OFF_V + offV + kb * 16 * LDE + dbg * 16) << 1));
                mma_f16(Oa[2 * dbp],     aP, bv);
                mma_f16(Oa[2 * dbp + 1], aP, bv + 2);
            }
        }
    }

    // ---- reduce half-row sums; publish ----
    ls0 += __shfl_xor_sync(0xffffffffu, ls0, 1);
    ls0 += __shfl_xor_sync(0xffffffffu, ls0, 2);
    ls1 += __shfl_xor_sync(0xffffffffu, ls1, 1);
    ls1 += __shfl_xor_sync(0xffffffffu, ls1, 2);
    if (ac == 0) {
        sL[h * 128 + m0 + ar]     = ls0;
        sL[h * 128 + m0 + ar + 8] = ls1;
    }
    __syncthreads();

    const float inv0 = 1.0f / (sL[m0 + ar]     + sL[128 + m0 + ar]);
    const float inv1 = 1.0f / (sL[m0 + ar + 8] + sL[128 + m0 + ar + 8]);

    // ---- store normalized O ----
    float* or0 = outp + ((size_t)(b * SEQ + gi0)) * DIM + h * 64 + 2 * ac;
    float* or1 = or0 + 8 * DIM;
    #pragma unroll
    for (int nb = 0; nb < 8; nb++) {
        *(float2*)(or0 + nb * 8) = make_float2(Oa[nb][0] * inv0, Oa[nb][1] * inv0);
        *(float2*)(or1 + nb * 8) = make_float2(Oa[nb][2] * inv1, Oa[nb][3] * inv1);
    }

    // ---- in-kernel finalize: rescale own rows, cols [i0, SEQ) ----
    {
        const int W1 = (SEQ - i0) / 4;
        for (int row = wid; row < TILE; row += 16) {
            const float inv = 1.0f / (sL[row] + sL[128 + row]);
            float4* wr = (float4*)(wts + ((size_t)(b * SEQ + i0 + row)) * SEQ + i0);
            for (int q = l; q < W1; q += 32) {
                float4 w = wr[q];
                w.x *= inv; w.y *= inv; w.z *= inv; w.w *= inv;
                wr[q] = w;
            }
        }
    }
}

extern "C" void kernel_launch(void* const* d_in, const int* in_sizes, int n_in,
                              void* d_out, int out_size) {
    const float* Q = (const float*)d_in[0];
    const float* K = (const float*)d_in[1];
    const float* V = (const float*)d_in[2];
    float* outp = (float*)d_out;
    float* wts  = outp + (size_t)BATCH * SEQ * DIM;

    dim3 pgrid(NELEM / 4 / 256, 3);
    conv_pre_kernel<<<pgrid, 256>>>(Q, K, V);

    cudaFuncSetAttribute(attn_mma_kernel,
                         cudaFuncAttributeMaxDynamicSharedMemorySize, SMEM_BYTES);
    dim3 grid(16, BATCH);
    attn_mma_kernel<<<grid, 512, SMEM_BYTES>>>(outp, wts);
}